// round 15
// baseline (speedup 1.0000x reference)
#include <cuda_runtime.h>
#include <cuda_bf16.h>

#define B 512
#define D 768
#define MARGIN 1.0f
#define KSPLIT 8
#define KPER 96     // 768 / 8
#define GRID 296    // 148 SMs x 2 CTA — all co-resident (barrier-safe)

// Scratch (allocation-free rule: __device__ globals)
__device__ float g_gramp[KSPLIT][B * B];  // K-split partial Gram planes, mirrored
__device__ float g_sqn[B];
__device__ double g_sum;
__device__ unsigned long long g_count;
__device__ unsigned int g_done;           // self-wrapping ticket
__device__ unsigned int g_bar;            // grid barrier; finisher re-arms

// ---------------------------------------------------------------------------
// ONE kernel, grid = 296 x 256, __launch_bounds__(256,2) caps regs at 128 so
// both CTAs fit per SM (the R5 fusion failure was an uncapped 244-reg build).
//  Phase 1: blocks 0..287 Gram (64x64 triangle tiles, 4x4 micro, K-split x8,
//           pipelined loads, mirrored plane stores); 288..295 sq-norms.
//  Grid barrier (296 co-resident CTAs).
//  Phase 2: blocks sweep anchors a = bid, bid+296; atomic-free compaction;
//           4-positives-in-registers hinge; finisher writes out + re-arms.
// ---------------------------------------------------------------------------
__global__ void __launch_bounds__(256, 2)
fused_kernel(const float* __restrict__ X, const int* __restrict__ types,
             float* __restrict__ out) {
    __shared__ float As[16][68];  // [k][row], padded
    __shared__ float Bs[16][68];
    __shared__ __align__(16) float posv[B + 4];
    __shared__ __align__(16) float negv[B + 4];
    __shared__ int wcnt[8];
    __shared__ float ws[8];

    int bid = blockIdx.x;
    int tid = threadIdx.x;
    int lane = tid & 31, warp = tid >> 5;

    // ======================== PHASE 1 ========================
    if (bid >= 288) {
        // ---- sq-norms: 64 rows per block ----
        int rb = (bid - 288) * 64;
        #pragma unroll
        for (int i = 0; i < 8; i++) {
            int row = rb + warp * 8 + i;
            const float4* rp = (const float4*)(X + (size_t)row * D);
            float acc = 0.f;
            #pragma unroll
            for (int q = 0; q < 6; q++) {
                float4 v = rp[lane + 32 * q];
                acc += v.x * v.x + v.y * v.y + v.z * v.z + v.w * v.w;
            }
            #pragma unroll
            for (int o = 16; o; o >>= 1) acc += __shfl_down_sync(0xffffffffu, acc, o);
            if (lane == 0) g_sqn[row] = acc;
        }
    } else {
        // ---- Gram: 64x64 triangle tiles, 4x4 micro-tile, K-split x8 ----
        int ks = bid & 7;
        int idx = bid >> 3, by = 0;  // tile 0..35 -> (by, bx), bx >= by
        for (;;) {
            int len = 8 - by;
            if (idx < len) break;
            idx -= len;
            by++;
        }
        int bx = by + idx;
        int rowBase = by * 64;
        int colBase = bx * 64;

        int tx = tid & 15, ty = tid >> 4;
        int lr = tid & 63;
        int lq = tid >> 6;

        const float* arow = X + (size_t)(rowBase + lr) * D + ks * KPER + lq * 4;
        const float* brow = X + (size_t)(colBase + lr) * D + ks * KPER + lq * 4;

        float acc[4][4];
        #pragma unroll
        for (int i = 0; i < 4; i++)
            #pragma unroll
            for (int j = 0; j < 4; j++) acc[i][j] = 0.f;

        float4 av = *(const float4*)arow;
        float4 bv = *(const float4*)brow;

        for (int kc = 0; kc < KPER; kc += 16) {
            As[lq * 4 + 0][lr] = av.x; As[lq * 4 + 1][lr] = av.y;
            As[lq * 4 + 2][lr] = av.z; As[lq * 4 + 3][lr] = av.w;
            Bs[lq * 4 + 0][lr] = bv.x; Bs[lq * 4 + 1][lr] = bv.y;
            Bs[lq * 4 + 2][lr] = bv.z; Bs[lq * 4 + 3][lr] = bv.w;
            __syncthreads();
            if (kc + 16 < KPER) {
                av = *(const float4*)(arow + kc + 16);
                bv = *(const float4*)(brow + kc + 16);
            }
            #pragma unroll
            for (int k = 0; k < 16; k++) {
                float4 a4 = *(const float4*)&As[k][ty * 4];
                float4 b4 = *(const float4*)&Bs[k][tx * 4];
                float a[4] = {a4.x, a4.y, a4.z, a4.w};
                float b[4] = {b4.x, b4.y, b4.z, b4.w};
                #pragma unroll
                for (int i = 0; i < 4; i++)
                    #pragma unroll
                    for (int j = 0; j < 4; j++) acc[i][j] += a[i] * b[j];
            }
            __syncthreads();
        }

        float* plane = g_gramp[ks];
        #pragma unroll
        for (int i = 0; i < 4; i++) {
            int r = rowBase + ty * 4 + i;
            *(float4*)&plane[r * B + colBase + tx * 4] =
                make_float4(acc[i][0], acc[i][1], acc[i][2], acc[i][3]);
        }
        if (bx != by) {
            #pragma unroll
            for (int j = 0; j < 4; j++) {
                int c = colBase + tx * 4 + j;
                *(float4*)&plane[c * B + rowBase + ty * 4] =
                    make_float4(acc[0][j], acc[1][j], acc[2][j], acc[3][j]);
            }
        }
    }

    // ============== grid barrier (all 296 CTAs resident) ==============
    __threadfence();
    __syncthreads();
    if (tid == 0) {
        atomicAdd(&g_bar, 1u);
        volatile unsigned* vb = &g_bar;
        while (*vb < GRID) { }
    }
    __syncthreads();
    __threadfence();

    // ======================== PHASE 2: triplets ========================
    double blockSum = 0.0;
    unsigned long long blockCnt = 0ull;
    unsigned lt_mask = (1u << lane) - 1u;

    for (int a = bid; a < B; a += GRID) {
        // ---- hoisted loads, all L2-hot (planes written moments ago) ----
        float2 v0 = ((const float2*)&g_gramp[0][a * B])[tid];
        float2 v1 = ((const float2*)&g_gramp[1][a * B])[tid];
        float2 v2 = ((const float2*)&g_gramp[2][a * B])[tid];
        float2 v3 = ((const float2*)&g_gramp[3][a * B])[tid];
        float2 v4 = ((const float2*)&g_gramp[4][a * B])[tid];
        float2 v5 = ((const float2*)&g_gramp[5][a * B])[tid];
        float2 v6 = ((const float2*)&g_gramp[6][a * B])[tid];
        float2 v7 = ((const float2*)&g_gramp[7][a * B])[tid];
        float2 sq = ((const float2*)g_sqn)[tid];
        int2   tt = ((const int2*)types)[tid];
        int ta = types[a];
        float sa = g_sqn[a];

        int ja = 2 * tid, jb = 2 * tid + 1;
        float ga = ((v0.x + v1.x) + (v2.x + v3.x)) + ((v4.x + v5.x) + (v6.x + v7.x));
        float gb = ((v0.y + v1.y) + (v2.y + v3.y)) + ((v4.y + v5.y) + (v6.y + v7.y));
        float dva = (ja == a) ? 0.f : sqrtf(fmaxf(sa + sq.x - 2.f * ga, 0.f));
        float dvb = (jb == a) ? 0.f : sqrtf(fmaxf(sa + sq.y - 2.f * gb, 0.f));
        bool pa = (tt.x == ta);
        bool pb = (tt.y == ta);

        // ---- atomic-free compaction (warp w owns j in [64w, 64w+64)) ----
        unsigned mpa = __ballot_sync(0xffffffffu, pa);
        unsigned mpb = __ballot_sync(0xffffffffu, pb);
        int cpa = __popc(mpa), cpb = __popc(mpb);
        if (lane == 0) wcnt[warp] = cpa + cpb;
        __syncthreads();

        int np = 0, base = 0;
        #pragma unroll
        for (int w = 0; w < 8; w++) {
            int c = wcnt[w];
            if (w < warp) base += c;
            np += c;
        }
        int nn = B - np;
        int nbase = warp * 64 - base;  // negatives before this warp

        if (pa) posv[base + __popc(mpa & lt_mask)] = dva;
        else    negv[nbase + __popc((~mpa) & lt_mask)] = dva;
        if (pb) posv[base + cpa + __popc(mpb & lt_mask)] = dvb;
        else    negv[nbase + (32 - cpa) + __popc((~mpb) & lt_mask)] = dvb;
        __syncthreads();

        int nn4 = (nn + 3) & ~3;
        int np4 = (np + 3) & ~3;
        if (tid < nn4 - nn) negv[nn + tid] = 1e30f;   // pad -> 0 contribution
        if (tid < np4 - np) posv[np + tid] = -1e30f;
        __syncthreads();

        const float4* negv4 = (const float4*)negv;
        int nq = nn4 >> 2;
        float a0 = 0.f, a1 = 0.f, a2 = 0.f, a3 = 0.f;
        for (int p = warp * 4; p < np4; p += 32) {
            float dp0 = posv[p + 0] + MARGIN;
            float dp1 = posv[p + 1] + MARGIN;
            float dp2 = posv[p + 2] + MARGIN;
            float dp3 = posv[p + 3] + MARGIN;
            for (int n = lane; n < nq; n += 32) {
                float4 v = negv4[n];
                a0 += fmaxf(dp0 - v.x, 0.f); a0 += fmaxf(dp0 - v.y, 0.f);
                a0 += fmaxf(dp0 - v.z, 0.f); a0 += fmaxf(dp0 - v.w, 0.f);
                a1 += fmaxf(dp1 - v.x, 0.f); a1 += fmaxf(dp1 - v.y, 0.f);
                a1 += fmaxf(dp1 - v.z, 0.f); a1 += fmaxf(dp1 - v.w, 0.f);
                a2 += fmaxf(dp2 - v.x, 0.f); a2 += fmaxf(dp2 - v.y, 0.f);
                a2 += fmaxf(dp2 - v.z, 0.f); a2 += fmaxf(dp2 - v.w, 0.f);
                a3 += fmaxf(dp3 - v.x, 0.f); a3 += fmaxf(dp3 - v.y, 0.f);
                a3 += fmaxf(dp3 - v.z, 0.f); a3 += fmaxf(dp3 - v.w, 0.f);
            }
        }
        float acc = (a0 + a1) + (a2 + a3);

        #pragma unroll
        for (int o = 16; o; o >>= 1) acc += __shfl_down_sync(0xffffffffu, acc, o);
        if (lane == 0) ws[warp] = acc;
        __syncthreads();
        if (tid == 0) {
            float s = 0.f;
            #pragma unroll
            for (int w = 0; w < 8; w++) s += ws[w];
            blockSum += (double)s;
            blockCnt += (unsigned long long)((long long)np * nn);
        }
        __syncthreads();  // smem reuse across anchor iterations
    }

    // ---- accumulate; last block finalizes and re-arms for next replay ----
    if (tid == 0) {
        atomicAdd(&g_sum, blockSum);
        atomicAdd(&g_count, blockCnt);
        __threadfence();
        unsigned d = atomicInc(&g_done, GRID - 1);  // wraps to 0 (self-reset)
        if (d == GRID - 1) {
            double S = atomicAdd(&g_sum, 0.0);
            unsigned long long C = atomicAdd(&g_count, 0ull);
            double V = (double)C;
            double b3 = 134217728.0;  // 512^3
            out[0] = (float)(((b3 - V) * (double)MARGIN + S) / V);
            // re-arm for the next graph replay
            g_sum = 0.0;
            g_count = 0ull;
            __threadfence();
            g_bar = 0u;
        }
    }
}

extern "C" void kernel_launch(void* const* d_in, const int* in_sizes, int n_in,
                              void* d_out, int out_size) {
    int ti = 0, ei = 1;
    if (in_sizes[0] == B * D) { ti = 1; ei = 0; }
    const int* types = (const int*)d_in[ti];
    const float* X = (const float*)d_in[ei];
    float* out = (float*)d_out;

    fused_kernel<<<GRID, 256>>>(X, types, out);
}

// round 17
// speedup vs baseline: 1.4243x; 1.4243x over previous
#include <cuda_runtime.h>
#include <cuda_bf16.h>
#include <cstdint>

#define B 512
#define D 768
#define MARGIN 1.0f

// Scratch (allocation-free rule: __device__ globals)
__device__ float g_gramp[4][B * B];  // K-split partial Gram planes (full matrix)
__device__ float g_sqn[B];
__device__ double g_sum;
__device__ unsigned long long g_count;
__device__ unsigned int g_done;

__device__ __forceinline__ uint32_t smem_u32(const void* p) {
    uint32_t a;
    asm("{ .reg .u64 t; cvta.to.shared.u64 t, %1; cvt.u32.u64 %0, t; }"
        : "=r"(a) : "l"(p));
    return a;
}

#define LDMATRIX_X4(r0, r1, r2, r3, addr) \
    asm volatile("ldmatrix.sync.aligned.m8n8.x4.shared.b16 {%0,%1,%2,%3}, [%4];" \
                 : "=r"(r0), "=r"(r1), "=r"(r2), "=r"(r3) : "r"(addr))

#define MMA_BF16(c, a0, a1, a2, a3, b0, b1) \
    asm volatile("mma.sync.aligned.m16n8k16.row.col.f32.bf16.bf16.f32 " \
                 "{%0,%1,%2,%3}, {%4,%5,%6,%7}, {%8,%9}, {%0,%1,%2,%3};" \
                 : "+f"((c)[0]), "+f"((c)[1]), "+f"((c)[2]), "+f"((c)[3]) \
                 : "r"(a0), "r"(a1), "r"(a2), "r"(a3), "r"(b0), "r"(b1))

// ---------------------------------------------------------------------------
// Kernel A: grid = 260 x 128 threads.
//   blocks 0..255 : Gram via warp-level bf16 HMMA (mma.sync m16n8k16).
//                   64x64 tiles over the FULL matrix (8x8 tile grid) x
//                   K-split 4 (192 K per block, 3 chunks of 64).
//                   fp32->bf16 smem tiles (row stride 72 bf16 = 144B);
//                   both A (.row) and B (.col) fragments come from identical
//                   non-trans ldmatrix.x4 on rows of X (Gram = X X^T).
//   blocks 256..259: sq-norms (fp32 exact, 128 rows each); 259 resets scalars
// ---------------------------------------------------------------------------
__global__ void __launch_bounds__(128)
gram_sqnorm_kernel(const float* __restrict__ X) {
    __shared__ __align__(16) __nv_bfloat16 sA[64 * 72];
    __shared__ __align__(16) __nv_bfloat16 sB[64 * 72];

    int bid = blockIdx.x;
    int tid = threadIdx.x;
    int lane = tid & 31, warp = tid >> 5;

    if (bid >= 256) {
        // ---- sq-norm path (fp32, exact) + scalar reset ----
        if (bid == 259 && tid == 0) {
            g_sum = 0.0;
            g_count = 0ull;
            g_done = 0u;
        }
        int rb = (bid - 256) * 128;
        #pragma unroll
        for (int i = 0; i < 32; i++) {
            int row = rb + warp * 32 + i;
            const float4* rp = (const float4*)(X + (size_t)row * D);
            float acc = 0.f;
            #pragma unroll
            for (int q = 0; q < 6; q++) {
                float4 v = rp[lane + 32 * q];
                acc += v.x * v.x + v.y * v.y + v.z * v.z + v.w * v.w;
            }
            #pragma unroll
            for (int o = 16; o; o >>= 1) acc += __shfl_down_sync(0xffffffffu, acc, o);
            if (lane == 0) g_sqn[row] = acc;
        }
        return;
    }

    // ---- HMMA Gram path ----
    int ks = bid & 3;            // K-slice 0..3 -> plane
    int tile = bid >> 2;         // 0..63 over 8x8 tile grid
    int rowBase = (tile >> 3) * 64;
    int colBase = (tile & 7) * 64;
    int warp_m = (warp & 1) * 32;
    int warp_n = (warp >> 1) * 32;

    uint32_t sA_u = smem_u32(sA);
    uint32_t sB_u = smem_u32(sB);

    float c[2][4][4];
    #pragma unroll
    for (int a = 0; a < 2; a++)
        #pragma unroll
        for (int b = 0; b < 4; b++)
            #pragma unroll
            for (int e = 0; e < 4; e++) c[a][b][e] = 0.f;

    // ldmatrix per-lane row address components (row = lane&15, colblk = lane>>4)
    int lrow = lane & 15;
    int lblk = lane >> 4;

    for (int chunk = 0; chunk < 3; chunk++) {
        int k0 = ks * 192 + chunk * 64;

        // fill both 64x64 bf16 tiles (8 float4 quads per thread per tile)
        #pragma unroll
        for (int i = 0; i < 8; i++) {
            int idx = i * 128 + tid;
            int r = idx >> 4, c4 = idx & 15;
            float4 va = *(const float4*)(X + (size_t)(rowBase + r) * D + k0 + c4 * 4);
            float4 vb = *(const float4*)(X + (size_t)(colBase + r) * D + k0 + c4 * 4);
            __nv_bfloat162 a0 = __float22bfloat162_rn(make_float2(va.x, va.y));
            __nv_bfloat162 a1 = __float22bfloat162_rn(make_float2(va.z, va.w));
            __nv_bfloat162 b0 = __float22bfloat162_rn(make_float2(vb.x, vb.y));
            __nv_bfloat162 b1 = __float22bfloat162_rn(make_float2(vb.z, vb.w));
            uint2 pa, pb;
            pa.x = *reinterpret_cast<uint32_t*>(&a0);
            pa.y = *reinterpret_cast<uint32_t*>(&a1);
            pb.x = *reinterpret_cast<uint32_t*>(&b0);
            pb.y = *reinterpret_cast<uint32_t*>(&b1);
            *(uint2*)&sA[r * 72 + c4 * 4] = pa;
            *(uint2*)&sB[r * 72 + c4 * 4] = pb;
        }
        __syncthreads();

        #pragma unroll
        for (int kk = 0; kk < 64; kk += 16) {
            // A fragments: 2 m16 atoms (rows warp_m + a*16 .. +15)
            uint32_t af[2][4];
            #pragma unroll
            for (int a = 0; a < 2; a++) {
                uint32_t addr = sA_u +
                    ((warp_m + a * 16 + lrow) * 72 + kk + lblk * 8) * 2;
                LDMATRIX_X4(af[a][0], af[a][1], af[a][2], af[a][3], addr);
            }
            // B fragments: 2 pairs, each covering n atoms {2p, 2p+1}
            uint32_t bf[2][4];
            #pragma unroll
            for (int p = 0; p < 2; p++) {
                uint32_t addr = sB_u +
                    ((warp_n + p * 16 + lrow) * 72 + kk + lblk * 8) * 2;
                LDMATRIX_X4(bf[p][0], bf[p][1], bf[p][2], bf[p][3], addr);
            }
            #pragma unroll
            for (int a = 0; a < 2; a++)
                #pragma unroll
                for (int b = 0; b < 4; b++)
                    MMA_BF16(c[a][b], af[a][0], af[a][1], af[a][2], af[a][3],
                             bf[b >> 1][b & 1], bf[b >> 1][2 + (b & 1)]);
        }
        __syncthreads();
    }

    // ---- epilogue: fragment -> plane stores (float2 per row-pair) ----
    float* plane = g_gramp[ks];
    int g = lane >> 2, tg = lane & 3;
    #pragma unroll
    for (int a = 0; a < 2; a++) {
        int r0 = rowBase + warp_m + a * 16 + g;
        #pragma unroll
        for (int b = 0; b < 4; b++) {
            int cc = colBase + warp_n + b * 8 + tg * 2;
            *(float2*)&plane[(size_t)r0 * B + cc] = make_float2(c[a][b][0], c[a][b][1]);
            *(float2*)&plane[(size_t)(r0 + 8) * B + cc] = make_float2(c[a][b][2], c[a][b][3]);
        }
    }
}

// ---------------------------------------------------------------------------
// Kernel B (round-11 proven, unchanged): one block per anchor. Hoisted wide
// loads; two ballot-compaction passes; 4-positives-in-registers hinge loop.
// Last block finalizes.
// ---------------------------------------------------------------------------
__global__ void __launch_bounds__(256)
triplet_kernel(const int* __restrict__ types, float* __restrict__ out) {
    int a = blockIdx.x;
    __shared__ __align__(16) float posv[B + 4];
    __shared__ __align__(16) float negv[B + 4];
    __shared__ int cnt[2];
    __shared__ float ws[8];
    int tid = threadIdx.x;
    int lane = tid & 31, warp = tid >> 5;
    if (tid < 2) cnt[tid] = 0;

    const float2* q0 = (const float2*)&g_gramp[0][a * B];
    const float2* q1 = (const float2*)&g_gramp[1][a * B];
    const float2* q2 = (const float2*)&g_gramp[2][a * B];
    const float2* q3 = (const float2*)&g_gramp[3][a * B];
    float2 v0 = q0[tid];
    float2 v1 = q1[tid];
    float2 v2 = q2[tid];
    float2 v3 = q3[tid];
    float2 sq = ((const float2*)g_sqn)[tid];
    int2   tt = ((const int2*)types)[tid];
    int ta = types[a];
    float sa = g_sqn[a];

    int ja = 2 * tid, jb = 2 * tid + 1;
    float ga = (v0.x + v1.x) + (v2.x + v3.x);
    float gb = (v0.y + v1.y) + (v2.y + v3.y);
    float dva = (ja == a) ? 0.f : sqrtf(fmaxf(sa + sq.x - 2.f * ga, 0.f));
    float dvb = (jb == a) ? 0.f : sqrtf(fmaxf(sa + sq.y - 2.f * gb, 0.f));
    bool pa = (tt.x == ta);
    bool pb = (tt.y == ta);

    __syncthreads();

    unsigned lt_mask = (1u << lane) - 1u;
    {
        unsigned mp = __ballot_sync(0xffffffffu, pa);
        int cp = __popc(mp);
        int bp = 0, bn = 0;
        if (lane == 0) {
            bp = atomicAdd(&cnt[0], cp);
            bn = atomicAdd(&cnt[1], 32 - cp);
        }
        bp = __shfl_sync(0xffffffffu, bp, 0);
        bn = __shfl_sync(0xffffffffu, bn, 0);
        if (pa) posv[bp + __popc(mp & lt_mask)] = dva;
        else    negv[bn + __popc((~mp) & lt_mask)] = dva;
    }
    {
        unsigned mp = __ballot_sync(0xffffffffu, pb);
        int cp = __popc(mp);
        int bp = 0, bn = 0;
        if (lane == 0) {
            bp = atomicAdd(&cnt[0], cp);
            bn = atomicAdd(&cnt[1], 32 - cp);
        }
        bp = __shfl_sync(0xffffffffu, bp, 0);
        bn = __shfl_sync(0xffffffffu, bn, 0);
        if (pb) posv[bp + __popc(mp & lt_mask)] = dvb;
        else    negv[bn + __popc((~mp) & lt_mask)] = dvb;
    }
    __syncthreads();

    int np = cnt[0], nn = cnt[1];
    int nn4 = (nn + 3) & ~3;
    int np4 = (np + 3) & ~3;
    if (tid < nn4 - nn) negv[nn + tid] = 1e30f;   // pad: max(dp - INF, 0) = 0
    if (tid < np4 - np) posv[np + tid] = -1e30f;  // pad: max(-INF - dn, 0) = 0
    __syncthreads();

    const float4* negv4 = (const float4*)negv;
    int nq = nn4 >> 2;
    float a0 = 0.f, a1 = 0.f, a2 = 0.f, a3 = 0.f;
    for (int p = warp * 4; p < np4; p += 32) {
        float dp0 = posv[p + 0] + MARGIN;
        float dp1 = posv[p + 1] + MARGIN;
        float dp2 = posv[p + 2] + MARGIN;
        float dp3 = posv[p + 3] + MARGIN;
        for (int n = lane; n < nq; n += 32) {
            float4 v = negv4[n];
            a0 += fmaxf(dp0 - v.x, 0.f); a0 += fmaxf(dp0 - v.y, 0.f);
            a0 += fmaxf(dp0 - v.z, 0.f); a0 += fmaxf(dp0 - v.w, 0.f);
            a1 += fmaxf(dp1 - v.x, 0.f); a1 += fmaxf(dp1 - v.y, 0.f);
            a1 += fmaxf(dp1 - v.z, 0.f); a1 += fmaxf(dp1 - v.w, 0.f);
            a2 += fmaxf(dp2 - v.x, 0.f); a2 += fmaxf(dp2 - v.y, 0.f);
            a2 += fmaxf(dp2 - v.z, 0.f); a2 += fmaxf(dp2 - v.w, 0.f);
            a3 += fmaxf(dp3 - v.x, 0.f); a3 += fmaxf(dp3 - v.y, 0.f);
            a3 += fmaxf(dp3 - v.z, 0.f); a3 += fmaxf(dp3 - v.w, 0.f);
        }
    }
    float acc = (a0 + a1) + (a2 + a3);

    #pragma unroll
    for (int o = 16; o; o >>= 1) acc += __shfl_down_sync(0xffffffffu, acc, o);
    if (lane == 0) ws[warp] = acc;
    __syncthreads();
    if (tid == 0) {
        float s = 0.f;
        #pragma unroll
        for (int w = 0; w < 8; w++) s += ws[w];
        atomicAdd(&g_sum, (double)s);
        atomicAdd(&g_count, (unsigned long long)((long long)np * nn));
        __threadfence();
        unsigned d = atomicInc(&g_done, 0xffffffffu);
        if (d == B - 1) {
            double S = atomicAdd(&g_sum, 0.0);
            unsigned long long C = atomicAdd(&g_count, 0ull);
            double V = (double)C;
            double b3 = 134217728.0;  // 512^3
            out[0] = (float)(((b3 - V) * (double)MARGIN + S) / V);
        }
    }
}

extern "C" void kernel_launch(void* const* d_in, const int* in_sizes, int n_in,
                              void* d_out, int out_size) {
    int ti = 0, ei = 1;
    if (in_sizes[0] == B * D) { ti = 1; ei = 0; }
    const int* types = (const int*)d_in[ti];
    const float* X = (const float*)d_in[ei];
    float* out = (float*)d_out;

    gram_sqnorm_kernel<<<260, 128>>>(X);
    triplet_kernel<<<B, 256>>>(types, out);
}